// round 5
// baseline (speedup 1.0000x reference)
#include <cuda_runtime.h>
#include <cstdint>

#define N_NODES 20000
#define N_EDGES 320000
#define TPW 4  // edges per warp per iteration

typedef unsigned long long ull;

// Scratch (device globals — no allocation allowed)
__device__ float g_sup[N_NODES * 64];                 // up-projected scalars [n][u]
__device__ float g_vup[N_NODES * 192];                // up-projected vectors [n][u][m]
// messages: [n][64][8] groups {s0, s1, v00, v01, v02, v10, v11, v12}
__device__ __align__(16) float g_msg[N_NODES * 512];

__device__ __forceinline__ float silu_f(float x) {
    return __fdividef(x, 1.0f + __expf(-x));
}

// ---- packed f32x2 helpers (sm_103a) ----
__device__ __forceinline__ ull pack2(float x, float y) {
    ull d; asm("mov.b64 %0, {%1, %2};" : "=l"(d) : "f"(x), "f"(y)); return d;
}
__device__ __forceinline__ void unpack2(ull v, float& x, float& y) {
    asm("mov.b64 {%0, %1}, %2;" : "=f"(x), "=f"(y) : "l"(v));
}
__device__ __forceinline__ ull fma2(ull a, ull b, ull c) {
    ull d; asm("fma.rn.f32x2 %0, %1, %2, %3;" : "=l"(d) : "l"(a), "l"(b), "l"(c)); return d;
}

// ---------------------------------------------------------------------------
// Zero the message accumulator
// ---------------------------------------------------------------------------
__global__ void zero_kernel() {
    int idx = blockIdx.x * blockDim.x + threadIdx.x;
    int stride = gridDim.x * blockDim.x;
    const int nm = N_NODES * 512 / 4;
    float4 z = make_float4(0.f, 0.f, 0.f, 0.f);
    for (int i = idx; i < nm; i += stride) ((float4*)g_msg)[i] = z;
}

// ---------------------------------------------------------------------------
// Node up-projection: s' = s @ W_up0 / 8 ; v' = einsum(num,uv->nvm) / 8
// 32-node tiles, 2 nodes per thread, packed f32x2 math.
// ---------------------------------------------------------------------------
#define NUP_SMEM ((4096 + 4096 + 32 * 256) * 4)

__global__ __launch_bounds__(256) void nodeup_kernel(
    const float* __restrict__ nf, const float* __restrict__ W0,
    const float* __restrict__ W1) {
    extern __shared__ float smem[];
    float* sW0 = smem;            // 64x64
    float* sW1 = sW0 + 4096;      // 64x64
    float* sx  = sW1 + 4096;      // 32 x 256
    int tid = threadIdx.x;
    for (int i = tid; i < 4096; i += 256) { sW0[i] = W0[i] * 0.125f; sW1[i] = W1[i] * 0.125f; }
    int ln = tid >> 4;          // local node 0..15 (pairs with ln+16)
    int cg = tid & 15;          // col group (4 cols)
    const ulonglong2* w0v = (const ulonglong2*)sW0;
    const ulonglong2* w1v = (const ulonglong2*)sW1;
    const int ntiles = N_NODES / 32;
    for (int tile = blockIdx.x; tile < ntiles; tile += gridDim.x) {
        int nb = tile * 32;
        __syncthreads();
        {
            const float4* src = (const float4*)(nf + (size_t)nb * 256);
            float4* dst = (float4*)sx;
            for (int i = tid; i < 2048; i += 256) dst[i] = src[i];
        }
        __syncthreads();
        const float* xA = sx + ln * 256;
        const float* xB = sx + (ln + 16) * 256;
        ull sA0 = 0, sA1 = 0, a0A0 = 0, a0A1 = 0, a1A0 = 0, a1A1 = 0, a2A0 = 0, a2A1 = 0;
        ull sB0 = 0, sB1 = 0, a0B0 = 0, a0B1 = 0, a1B0 = 0, a1B1 = 0, a2B0 = 0, a2B1 = 0;
#pragma unroll 4
        for (int u = 0; u < 64; u++) {
            ulonglong2 w0 = w0v[u * 16 + cg];
            ulonglong2 w1 = w1v[u * 16 + cg];
            {
                ull ps = pack2(xA[u], xA[u]);
                ull p0 = pack2(xA[64 + 3 * u], xA[64 + 3 * u]);
                ull p1 = pack2(xA[64 + 3 * u + 1], xA[64 + 3 * u + 1]);
                ull p2 = pack2(xA[64 + 3 * u + 2], xA[64 + 3 * u + 2]);
                sA0 = fma2(ps, w0.x, sA0);   sA1 = fma2(ps, w0.y, sA1);
                a0A0 = fma2(p0, w1.x, a0A0); a0A1 = fma2(p0, w1.y, a0A1);
                a1A0 = fma2(p1, w1.x, a1A0); a1A1 = fma2(p1, w1.y, a1A1);
                a2A0 = fma2(p2, w1.x, a2A0); a2A1 = fma2(p2, w1.y, a2A1);
            }
            {
                ull ps = pack2(xB[u], xB[u]);
                ull p0 = pack2(xB[64 + 3 * u], xB[64 + 3 * u]);
                ull p1 = pack2(xB[64 + 3 * u + 1], xB[64 + 3 * u + 1]);
                ull p2 = pack2(xB[64 + 3 * u + 2], xB[64 + 3 * u + 2]);
                sB0 = fma2(ps, w0.x, sB0);   sB1 = fma2(ps, w0.y, sB1);
                a0B0 = fma2(p0, w1.x, a0B0); a0B1 = fma2(p0, w1.y, a0B1);
                a1B0 = fma2(p1, w1.x, a1B0); a1B1 = fma2(p1, w1.y, a1B1);
                a2B0 = fma2(p2, w1.x, a2B0); a2B1 = fma2(p2, w1.y, a2B1);
            }
        }
#pragma unroll
        for (int h = 0; h < 2; h++) {
            int n = nb + ln + 16 * h;
            float4 aS, a0, a1, a2;
            if (h == 0) {
                unpack2(sA0, aS.x, aS.y);  unpack2(sA1, aS.z, aS.w);
                unpack2(a0A0, a0.x, a0.y); unpack2(a0A1, a0.z, a0.w);
                unpack2(a1A0, a1.x, a1.y); unpack2(a1A1, a1.z, a1.w);
                unpack2(a2A0, a2.x, a2.y); unpack2(a2A1, a2.z, a2.w);
            } else {
                unpack2(sB0, aS.x, aS.y);  unpack2(sB1, aS.z, aS.w);
                unpack2(a0B0, a0.x, a0.y); unpack2(a0B1, a0.z, a0.w);
                unpack2(a1B0, a1.x, a1.y); unpack2(a1B1, a1.z, a1.w);
                unpack2(a2B0, a2.x, a2.y); unpack2(a2B1, a2.z, a2.w);
            }
            *(float4*)(g_sup + (size_t)n * 64 + 4 * cg) = aS;
            float* vp = g_vup + (size_t)n * 192 + 12 * cg;
            ((float4*)vp)[0] = make_float4(a0.x, a1.x, a2.x, a0.y);
            ((float4*)vp)[1] = make_float4(a1.y, a2.y, a0.z, a1.z);
            ((float4*)vp)[2] = make_float4(a2.z, a0.w, a1.w, a2.w);
        }
    }
}

// ---------------------------------------------------------------------------
// Fused edge kernel: MLP(8->64->64->64->256) all in packed f32x2
//   layers 1-3: pairs over edges; layer 4: pairs over columns.
// -> message build -> scalar atomic scatter into g_msg[n][64][8].
// ---------------------------------------------------------------------------
#define EDGE_SMEM ((512 + 4096 + 4096 + 16384 + 8 * TPW * 64) * 4)

__global__ __launch_bounds__(256, 2) void edge_kernel(
    const float* __restrict__ edge_attrs, const float* __restrict__ edge_feats,
    const int* __restrict__ snd_idx, const int* __restrict__ rcv_idx,
    const float* __restrict__ M1, const float* __restrict__ M2,
    const float* __restrict__ M3, const float* __restrict__ M4) {
    extern __shared__ float smem[];
    float* sM1 = smem;
    float* sM2 = sM1 + 512;
    float* sM3 = sM2 + 4096;
    float* sM4 = sM3 + 4096;   // pair-permuted, pre-scaled by 1/8
    float* sh  = sM4 + 16384;
    int tid = threadIdx.x;
    for (int i = tid; i < 512;  i += 256) sM1[i] = M1[i];
    for (int i = tid; i < 4096; i += 256) { sM2[i] = M2[i]; sM3[i] = M3[i]; }
    // Permute M4 so that for each row i, the pair (col 32j+l, col 32j+32+l)
    // is stored adjacently: dest = i*256 + (jp*32 + l)*2 + half, j = 2*jp+half.
    for (int idx = tid; idx < 16384; idx += 256) {
        int i = idx >> 8, c = idx & 255;
        int j = c >> 5, lc = c & 31, jp = j >> 1, half = j & 1;
        sM4[(i << 8) + (((jp << 5) + lc) << 1) + half] = M4[idx] * 0.125f;
    }
    __syncthreads();

    int warp = tid >> 5, lane = tid & 31;
    float* hh = sh + warp * (TPW * 64);
    const int ngroups = N_EDGES / TPW;
    const float INV_SQRT3 = 0.57735026918962576f;
    const float S1 = 0.35355339059327379f;  // 1/sqrt(8)

    for (int g = blockIdx.x * 8 + warp; g < ngroups; g += gridDim.x * 8) {
        int e0 = g * TPW;
        // ---- layer 1 : ef(8) @ M1 -> h(64), silu. Pairs over edges. ----
        float ef[TPW][8];
#pragma unroll
        for (int t = 0; t < TPW; t++) {
            const float4* p = (const float4*)(edge_feats + (size_t)(e0 + t) * 8);
            float4 A = __ldg(p), B = __ldg(p + 1);
            ef[t][0] = A.x; ef[t][1] = A.y; ef[t][2] = A.z; ef[t][3] = A.w;
            ef[t][4] = B.x; ef[t][5] = B.y; ef[t][6] = B.z; ef[t][7] = B.w;
        }
        // acc2[p][c] = (val(edge 2p, col 2lane+c), val(edge 2p+1, col 2lane+c))
        ull acc2[2][2];
        acc2[0][0] = 0; acc2[0][1] = 0; acc2[1][0] = 0; acc2[1][1] = 0;
#pragma unroll
        for (int i = 0; i < 8; i++) {
            float2 w = *(const float2*)&sM1[i * 64 + 2 * lane];
            ull wx = pack2(w.x, w.x), wy = pack2(w.y, w.y);
            ull a01 = pack2(ef[0][i], ef[1][i]);
            ull a23 = pack2(ef[2][i], ef[3][i]);
            acc2[0][0] = fma2(a01, wx, acc2[0][0]);
            acc2[0][1] = fma2(a01, wy, acc2[0][1]);
            acc2[1][0] = fma2(a23, wx, acc2[1][0]);
            acc2[1][1] = fma2(a23, wy, acc2[1][1]);
        }
#pragma unroll
        for (int p = 0; p < 2; p++) {
            float x0, x1, y0, y1;
            unpack2(acc2[p][0], x0, x1);
            unpack2(acc2[p][1], y0, y1);
            float2 h0, h1;
            h0.x = silu_f(x0 * S1); h0.y = silu_f(y0 * S1);
            h1.x = silu_f(x1 * S1); h1.y = silu_f(y1 * S1);
            *(float2*)&hh[(2 * p) * 64 + 2 * lane]     = h0;
            *(float2*)&hh[(2 * p + 1) * 64 + 2 * lane] = h1;
        }
        __syncwarp();

        // ---- layers 2 & 3 : pairs over edges ----
#pragma unroll
        for (int L = 0; L < 2; L++) {
            const float* W = (L == 0) ? sM2 : sM3;
            ull b2[2][2];
            b2[0][0] = 0; b2[0][1] = 0; b2[1][0] = 0; b2[1][1] = 0;
            for (int i = 0; i < 64; i += 4) {
                float ha[TPW][4];
#pragma unroll
                for (int t = 0; t < TPW; t++)
                    *(float4*)ha[t] = *(const float4*)&hh[t * 64 + i];
#pragma unroll
                for (int k = 0; k < 4; k++) {
                    float2 w = *(const float2*)&W[(i + k) * 64 + 2 * lane];
                    ull wx = pack2(w.x, w.x), wy = pack2(w.y, w.y);
                    ull a01 = pack2(ha[0][k], ha[1][k]);
                    ull a23 = pack2(ha[2][k], ha[3][k]);
                    b2[0][0] = fma2(a01, wx, b2[0][0]);
                    b2[0][1] = fma2(a01, wy, b2[0][1]);
                    b2[1][0] = fma2(a23, wx, b2[1][0]);
                    b2[1][1] = fma2(a23, wy, b2[1][1]);
                }
            }
            __syncwarp();
#pragma unroll
            for (int p = 0; p < 2; p++) {
                float x0, x1, y0, y1;
                unpack2(b2[p][0], x0, x1);
                unpack2(b2[p][1], y0, y1);
                float2 h0, h1;
                h0.x = silu_f(x0 * 0.125f); h0.y = silu_f(y0 * 0.125f);
                h1.x = silu_f(x1 * 0.125f); h1.y = silu_f(y1 * 0.125f);
                *(float2*)&hh[(2 * p) * 64 + 2 * lane]     = h0;
                *(float2*)&hh[(2 * p + 1) * 64 + 2 * lane] = h1;
            }
            __syncwarp();
        }

        // ---- layer 4 : pairs over columns (pair-permuted sM4) ----
        ull a4p[TPW][4];
#pragma unroll
        for (int t = 0; t < TPW; t++)
#pragma unroll
            for (int jp = 0; jp < 4; jp++) a4p[t][jp] = 0ull;
        for (int i = 0; i < 64; i += 4) {
            float ha[TPW][4];
#pragma unroll
            for (int t = 0; t < TPW; t++)
                *(float4*)ha[t] = *(const float4*)&hh[t * 64 + i];
#pragma unroll
            for (int k = 0; k < 4; k++) {
                const float* wr = &sM4[((i + k) << 8) + 2 * lane];
                ull wp0 = *(const ull*)(wr);
                ull wp1 = *(const ull*)(wr + 64);
                ull wp2 = *(const ull*)(wr + 128);
                ull wp3 = *(const ull*)(wr + 192);
#pragma unroll
                for (int t = 0; t < TPW; t++) {
                    ull aa = pack2(ha[t][k], ha[t][k]);
                    a4p[t][0] = fma2(aa, wp0, a4p[t][0]);
                    a4p[t][1] = fma2(aa, wp1, a4p[t][1]);
                    a4p[t][2] = fma2(aa, wp2, a4p[t][2]);
                    a4p[t][3] = fma2(aa, wp3, a4p[t][3]);
                }
            }
        }

        // ---- message construction + scalar atomic scatter ----
#pragma unroll
        for (int t = 0; t < TPW; t++) {
            int e = e0 + t;
            int snd = __ldg(&snd_idx[e]);
            int rcv = __ldg(&rcv_idx[e]);
            float4 ea = __ldg((const float4*)(edge_attrs + (size_t)e * 4));
            float ys = ea.x, yv0 = ea.y, yv1 = ea.z, yv2 = ea.w;
            const float* sup = g_sup + (size_t)snd * 64;
            const float* vup = g_vup + (size_t)snd * 192;
            float* mb = g_msg + (size_t)rcv * 512;
            float w0a, w0b, w1a, w1b, w2a, w2b, w3a, w3b;
            unpack2(a4p[t][0], w0a, w0b);
            unpack2(a4p[t][1], w1a, w1b);
            unpack2(a4p[t][2], w2a, w2b);
            unpack2(a4p[t][3], w3a, w3b);
#pragma unroll
            for (int j = 0; j < 2; j++) {
                int u = lane + 32 * j;
                float xs  = __ldg(sup + u);
                float xv0 = __ldg(vup + 3 * u);
                float xv1 = __ldg(vup + 3 * u + 1);
                float xv2 = __ldg(vup + 3 * u + 2);
                float w0 = j ? w0b : w0a;
                float w1 = j ? w1b : w1a;
                float w2 = j ? w2b : w2a;
                float w3 = j ? w3b : w3a;
                float dv = xv0 * yv0 + xv1 * yv1 + xv2 * yv2;
                float wxs = w1 * xs;
                float wys = w2 * ys;
                float* dst = mb + u * 8;
                atomicAdd(dst,     w0 * xs * ys);
                atomicAdd(dst + 1, w3 * dv * INV_SQRT3);
                atomicAdd(dst + 2, wxs * yv0);
                atomicAdd(dst + 3, wxs * yv1);
                atomicAdd(dst + 4, wxs * yv2);
                atomicAdd(dst + 5, wys * xv0);
                atomicAdd(dst + 6, wys * xv1);
                atomicAdd(dst + 7, wys * xv2);
            }
        }
    }
}

// ---------------------------------------------------------------------------
// Node output from g_msg[n][64][8]:
//   out_s[v]    = sum_u g[u][0] W0[u][v] + g[u][1] W0[64+u][v]
//   out_v[v][m] = sum_u g[u][2+m] W1[u][v] + g[u][5+m] W1[64+u][v]
// 32-node tiles, 2 nodes per thread, packed f32x2.
// ---------------------------------------------------------------------------
#define NODEOUT_SMEM ((8192 + 8192 + 32 * 512) * 4)

__global__ __launch_bounds__(256) void nodeout_kernel(
    const float* __restrict__ WL0, const float* __restrict__ WL1,
    float* __restrict__ out) {
    extern __shared__ float smem[];
    float* sW0 = smem;            // 128x64
    float* sW1 = sW0 + 8192;      // 128x64
    float* sG  = sW1 + 8192;      // 32 x 512
    int tid = threadIdx.x;
    const float SC = 0.0055242717280199021f;  // 1/(sqrt(128)*16)
    for (int i = tid; i < 8192; i += 256) { sW0[i] = WL0[i] * SC; sW1[i] = WL1[i] * SC; }
    int ln = tid >> 4;
    int cg = tid & 15;
    const ulonglong2* w0v = (const ulonglong2*)sW0;
    const ulonglong2* w1v = (const ulonglong2*)sW1;
    const int ntiles = N_NODES / 32;
    for (int tile = blockIdx.x; tile < ntiles; tile += gridDim.x) {
        int nb = tile * 32;
        __syncthreads();
        {
            const float4* src = (const float4*)(g_msg + (size_t)nb * 512);
            float4* dst = (float4*)sG;
            for (int i = tid; i < 4096; i += 256) dst[i] = src[i];
        }
        __syncthreads();
        const float4* GA = (const float4*)(sG + ln * 512);
        const float4* GB = (const float4*)(sG + (ln + 16) * 512);
        ull sA0 = 0, sA1 = 0, a0A0 = 0, a0A1 = 0, a1A0 = 0, a1A1 = 0, a2A0 = 0, a2A1 = 0;
        ull sB0 = 0, sB1 = 0, a0B0 = 0, a0B1 = 0, a1B0 = 0, a1B1 = 0, a2B0 = 0, a2B1 = 0;
#pragma unroll 2
        for (int u = 0; u < 64; u++) {
            ulonglong2 w0a = w0v[u * 16 + cg];
            ulonglong2 w0b = w0v[(64 + u) * 16 + cg];
            ulonglong2 w1a = w1v[u * 16 + cg];
            ulonglong2 w1b = w1v[(64 + u) * 16 + cg];
            {
                float4 g0 = GA[u * 2];       // s0, s1, v00, v01
                float4 g1 = GA[u * 2 + 1];   // v02, v10, v11, v12
                ull p;
                p = pack2(g0.x, g0.x); sA0 = fma2(p, w0a.x, sA0);  sA1 = fma2(p, w0a.y, sA1);
                p = pack2(g0.y, g0.y); sA0 = fma2(p, w0b.x, sA0);  sA1 = fma2(p, w0b.y, sA1);
                p = pack2(g0.z, g0.z); a0A0 = fma2(p, w1a.x, a0A0); a0A1 = fma2(p, w1a.y, a0A1);
                p = pack2(g1.y, g1.y); a0A0 = fma2(p, w1b.x, a0A0); a0A1 = fma2(p, w1b.y, a0A1);
                p = pack2(g0.w, g0.w); a1A0 = fma2(p, w1a.x, a1A0); a1A1 = fma2(p, w1a.y, a1A1);
                p = pack2(g1.z, g1.z); a1A0 = fma2(p, w1b.x, a1A0); a1A1 = fma2(p, w1b.y, a1A1);
                p = pack2(g1.x, g1.x); a2A0 = fma2(p, w1a.x, a2A0); a2A1 = fma2(p, w1a.y, a2A1);
                p = pack2(g1.w, g1.w); a2A0 = fma2(p, w1b.x, a2A0); a2A1 = fma2(p, w1b.y, a2A1);
            }
            {
                float4 g0 = GB[u * 2];
                float4 g1 = GB[u * 2 + 1];
                ull p;
                p = pack2(g0.x, g0.x); sB0 = fma2(p, w0a.x, sB0);  sB1 = fma2(p, w0a.y, sB1);
                p = pack2(g0.y, g0.y); sB0 = fma2(p, w0b.x, sB0);  sB1 = fma2(p, w0b.y, sB1);
                p = pack2(g0.z, g0.z); a0B0 = fma2(p, w1a.x, a0B0); a0B1 = fma2(p, w1a.y, a0B1);
                p = pack2(g1.y, g1.y); a0B0 = fma2(p, w1b.x, a0B0); a0B1 = fma2(p, w1b.y, a0B1);
                p = pack2(g0.w, g0.w); a1B0 = fma2(p, w1a.x, a1B0); a1B1 = fma2(p, w1a.y, a1B1);
                p = pack2(g1.z, g1.z); a1B0 = fma2(p, w1b.x, a1B0); a1B1 = fma2(p, w1b.y, a1B1);
                p = pack2(g1.x, g1.x); a2B0 = fma2(p, w1a.x, a2B0); a2B1 = fma2(p, w1a.y, a2B1);
                p = pack2(g1.w, g1.w); a2B0 = fma2(p, w1b.x, a2B0); a2B1 = fma2(p, w1b.y, a2B1);
            }
        }
#pragma unroll
        for (int h = 0; h < 2; h++) {
            int n = nb + ln + 16 * h;
            float4 aS, a0, a1, a2;
            if (h == 0) {
                unpack2(sA0, aS.x, aS.y);  unpack2(sA1, aS.z, aS.w);
                unpack2(a0A0, a0.x, a0.y); unpack2(a0A1, a0.z, a0.w);
                unpack2(a1A0, a1.x, a1.y); unpack2(a1A1, a1.z, a1.w);
                unpack2(a2A0, a2.x, a2.y); unpack2(a2A1, a2.z, a2.w);
            } else {
                unpack2(sB0, aS.x, aS.y);  unpack2(sB1, aS.z, aS.w);
                unpack2(a0B0, a0.x, a0.y); unpack2(a0B1, a0.z, a0.w);
                unpack2(a1B0, a1.x, a1.y); unpack2(a1B1, a1.z, a1.w);
                unpack2(a2B0, a2.x, a2.y); unpack2(a2B1, a2.z, a2.w);
            }
            float* o = out + (size_t)n * 256;
            *(float4*)(o + 4 * cg) = aS;
            float* vp = o + 64 + 12 * cg;
            ((float4*)vp)[0] = make_float4(a0.x, a1.x, a2.x, a0.y);
            ((float4*)vp)[1] = make_float4(a1.y, a2.y, a0.z, a1.z);
            ((float4*)vp)[2] = make_float4(a2.z, a0.w, a1.w, a2.w);
        }
    }
}

// ---------------------------------------------------------------------------
extern "C" void kernel_launch(void* const* d_in, const int* in_sizes, int n_in,
                              void* d_out, int out_size) {
    const float* node_feats = (const float*)d_in[1];
    const float* edge_attrs = (const float*)d_in[2];
    const float* edge_feats = (const float*)d_in[3];
    const int*   eidx       = (const int*)d_in[4];
    const float* W_up0      = (const float*)d_in[5];
    const float* W_up1      = (const float*)d_in[6];
    const float* M1         = (const float*)d_in[7];
    const float* M2         = (const float*)d_in[8];
    const float* M3         = (const float*)d_in[9];
    const float* M4         = (const float*)d_in[10];
    const float* WL0        = (const float*)d_in[11];
    const float* WL1        = (const float*)d_in[12];
    float* out = (float*)d_out;

    cudaFuncSetAttribute(edge_kernel,
                         cudaFuncAttributeMaxDynamicSharedMemorySize, EDGE_SMEM);
    cudaFuncSetAttribute(nodeout_kernel,
                         cudaFuncAttributeMaxDynamicSharedMemorySize, NODEOUT_SMEM);
    cudaFuncSetAttribute(nodeup_kernel,
                         cudaFuncAttributeMaxDynamicSharedMemorySize, NUP_SMEM);

    zero_kernel<<<256, 256>>>();
    nodeup_kernel<<<296, 256, NUP_SMEM>>>(node_feats, W_up0, W_up1);
    edge_kernel<<<296, 256, EDGE_SMEM>>>(edge_attrs, edge_feats,
                                         eidx, eidx + N_EDGES, M1, M2, M3, M4);
    nodeout_kernel<<<148, 256, NODEOUT_SMEM>>>(WL0, WL1, out);
}

// round 6
// speedup vs baseline: 1.9693x; 1.9693x over previous
#include <cuda_runtime.h>
#include <cstdint>

#define N_NODES 20000
#define N_EDGES 320000
#define TPW 4  // edges per warp per iteration

typedef unsigned long long ull;

// Scratch (device globals — no allocation allowed)
__device__ float g_sup[N_NODES * 64];    // up-projected scalars  [n][u]
__device__ float g_vup[N_NODES * 192];   // up-projected vectors  [n][u][m]
__device__ float g_msgs[N_NODES * 128];  // scalar messages       [n][u]   (m_s0 | m_s1)
__device__ float g_msgv[N_NODES * 384];  // vector messages       [n][m][p] (p<64: v0, p>=64: v1)

__device__ __forceinline__ float silu_f(float x) {
    return __fdividef(x, 1.0f + __expf(-x));
}

// ---- packed f32x2 helpers (sm_103a) ----
__device__ __forceinline__ ull pack2(float x, float y) {
    ull d; asm("mov.b64 %0, {%1, %2};" : "=l"(d) : "f"(x), "f"(y)); return d;
}
__device__ __forceinline__ void unpack2(ull v, float& x, float& y) {
    asm("mov.b64 {%0, %1}, %2;" : "=f"(x), "=f"(y) : "l"(v));
}
__device__ __forceinline__ ull fma2(ull a, ull b, ull c) {
    ull d; asm("fma.rn.f32x2 %0, %1, %2, %3;" : "=l"(d) : "l"(a), "l"(b), "l"(c)); return d;
}

// ---------------------------------------------------------------------------
// Zero the message accumulators
// ---------------------------------------------------------------------------
__global__ void zero_kernel() {
    int idx = blockIdx.x * blockDim.x + threadIdx.x;
    int stride = gridDim.x * blockDim.x;
    const int ns = N_NODES * 128 / 4;
    const int nv = N_NODES * 384 / 4;
    float4 z = make_float4(0.f, 0.f, 0.f, 0.f);
    for (int i = idx; i < ns; i += stride) ((float4*)g_msgs)[i] = z;
    for (int i = idx; i < nv; i += stride) ((float4*)g_msgv)[i] = z;
}

// ---------------------------------------------------------------------------
// Node up-projection: s' = s @ W_up0 / 8 ; v' = einsum(num,uv->nvm) / 8
// ---------------------------------------------------------------------------
#define NUP_SMEM ((4096 + 4096 + 16 * 256) * 4)

__global__ __launch_bounds__(256) void nodeup_kernel(
    const float* __restrict__ nf, const float* __restrict__ W0,
    const float* __restrict__ W1) {
    extern __shared__ float smem[];
    float* sW0 = smem;            // 64x64
    float* sW1 = sW0 + 4096;      // 64x64
    float* sx  = sW1 + 4096;      // 16 x 256
    int tid = threadIdx.x;
    for (int i = tid; i < 4096; i += 256) { sW0[i] = W0[i] * 0.125f; sW1[i] = W1[i] * 0.125f; }
    int ln = tid >> 4;          // local node 0..15
    int cg = tid & 15;          // col group (4 cols)
    const float4* w0v = (const float4*)sW0;
    const float4* w1v = (const float4*)sW1;
    const int ntiles = N_NODES / 16;
    for (int tile = blockIdx.x; tile < ntiles; tile += gridDim.x) {
        int nb = tile * 16;
        __syncthreads();
        {
            const float4* src = (const float4*)(nf + (size_t)nb * 256);
            float4* dst = (float4*)sx;
            for (int i = tid; i < 1024; i += 256) dst[i] = src[i];
        }
        __syncthreads();
        const float* x = sx + ln * 256;
        float4 aS = make_float4(0.f, 0.f, 0.f, 0.f);
        float4 a0 = aS, a1 = aS, a2 = aS;
#pragma unroll 4
        for (int u = 0; u < 64; u++) {
            float4 w0 = w0v[u * 16 + cg];
            float4 w1 = w1v[u * 16 + cg];
            float s  = x[u];
            float v0 = x[64 + 3 * u], v1 = x[64 + 3 * u + 1], v2 = x[64 + 3 * u + 2];
            aS.x += s * w0.x; aS.y += s * w0.y; aS.z += s * w0.z; aS.w += s * w0.w;
            a0.x += v0 * w1.x; a0.y += v0 * w1.y; a0.z += v0 * w1.z; a0.w += v0 * w1.w;
            a1.x += v1 * w1.x; a1.y += v1 * w1.y; a1.z += v1 * w1.z; a1.w += v1 * w1.w;
            a2.x += v2 * w1.x; a2.y += v2 * w1.y; a2.z += v2 * w1.z; a2.w += v2 * w1.w;
        }
        int n = nb + ln;
        *(float4*)(g_sup + (size_t)n * 64 + 4 * cg) = aS;
        float* vp = g_vup + (size_t)n * 192 + 12 * cg;
        ((float4*)vp)[0] = make_float4(a0.x, a1.x, a2.x, a0.y);
        ((float4*)vp)[1] = make_float4(a1.y, a2.y, a0.z, a1.z);
        ((float4*)vp)[2] = make_float4(a2.z, a0.w, a1.w, a2.w);
    }
}

// ---------------------------------------------------------------------------
// Fused edge kernel: MLP(8->64->64->64->256) -> message build -> atomic scatter
// Layers 2/3: edge-pair packed f32x2. Layer 4: column-pair packed f32x2.
// Scatter: R2-style lane-coalesced scalar atomics (1 line per instruction).
// ---------------------------------------------------------------------------
#define EDGE_SMEM ((512 + 4096 + 4096 + 16384 + 8 * TPW * 64) * 4)

__global__ __launch_bounds__(256, 2) void edge_kernel(
    const float* __restrict__ edge_attrs, const float* __restrict__ edge_feats,
    const int* __restrict__ snd_idx, const int* __restrict__ rcv_idx,
    const float* __restrict__ M1, const float* __restrict__ M2,
    const float* __restrict__ M3, const float* __restrict__ M4) {
    extern __shared__ float smem[];
    float* sM1 = smem;
    float* sM2 = sM1 + 512;
    float* sM3 = sM2 + 4096;
    float* sM4 = sM3 + 4096;   // pair-permuted, pre-scaled by 1/8
    float* sh  = sM4 + 16384;
    int tid = threadIdx.x;
    for (int i = tid; i < 512;  i += 256) sM1[i] = M1[i];
    for (int i = tid; i < 4096; i += 256) { sM2[i] = M2[i]; sM3[i] = M3[i]; }
    // Permute M4 so that for each row i, the pair (col 32j+l, col 32j+32+l)
    // is stored adjacently: dest = i*256 + (jp*32 + l)*2 + half, j = 2*jp+half.
    for (int idx = tid; idx < 16384; idx += 256) {
        int i = idx >> 8, c = idx & 255;
        int j = c >> 5, lc = c & 31, jp = j >> 1, half = j & 1;
        sM4[(i << 8) + (((jp << 5) + lc) << 1) + half] = M4[idx] * 0.125f;
    }
    __syncthreads();

    int warp = tid >> 5, lane = tid & 31;
    float* hh = sh + warp * (TPW * 64);
    const int ngroups = N_EDGES / TPW;
    const float INV_SQRT3 = 0.57735026918962576f;
    const float S1 = 0.35355339059327379f;  // 1/sqrt(8)

    for (int g = blockIdx.x * 8 + warp; g < ngroups; g += gridDim.x * 8) {
        int e0 = g * TPW;
        // ---- layer 1 : ef(8) @ M1 -> h(64), silu ----
        float ef[TPW][8];
#pragma unroll
        for (int t = 0; t < TPW; t++) {
            const float4* p = (const float4*)(edge_feats + (size_t)(e0 + t) * 8);
            float4 A = __ldg(p), B = __ldg(p + 1);
            ef[t][0] = A.x; ef[t][1] = A.y; ef[t][2] = A.z; ef[t][3] = A.w;
            ef[t][4] = B.x; ef[t][5] = B.y; ef[t][6] = B.z; ef[t][7] = B.w;
        }
        float acc[TPW][2];
#pragma unroll
        for (int t = 0; t < TPW; t++) { acc[t][0] = 0.f; acc[t][1] = 0.f; }
#pragma unroll
        for (int i = 0; i < 8; i++) {
            float2 w = *(const float2*)&sM1[i * 64 + 2 * lane];
#pragma unroll
            for (int t = 0; t < TPW; t++) {
                acc[t][0] += ef[t][i] * w.x;
                acc[t][1] += ef[t][i] * w.y;
            }
        }
#pragma unroll
        for (int t = 0; t < TPW; t++) {
            float2 hv;
            hv.x = silu_f(acc[t][0] * S1);
            hv.y = silu_f(acc[t][1] * S1);
            *(float2*)&hh[t * 64 + 2 * lane] = hv;
        }
        __syncwarp();

        // ---- layers 2 & 3 : edge-pair packed f32x2 ----
#pragma unroll
        for (int L = 0; L < 2; L++) {
            const float* W = (L == 0) ? sM2 : sM3;
            // b2[p][c] = (val(edge 2p, col 2lane+c), val(edge 2p+1, col 2lane+c))
            ull b2[2][2];
            b2[0][0] = 0; b2[0][1] = 0; b2[1][0] = 0; b2[1][1] = 0;
            for (int i = 0; i < 64; i += 4) {
                float ha[TPW][4];
#pragma unroll
                for (int t = 0; t < TPW; t++)
                    *(float4*)ha[t] = *(const float4*)&hh[t * 64 + i];
#pragma unroll
                for (int k = 0; k < 4; k++) {
                    float2 w = *(const float2*)&W[(i + k) * 64 + 2 * lane];
                    ull wx = pack2(w.x, w.x), wy = pack2(w.y, w.y);
                    ull a01 = pack2(ha[0][k], ha[1][k]);
                    ull a23 = pack2(ha[2][k], ha[3][k]);
                    b2[0][0] = fma2(a01, wx, b2[0][0]);
                    b2[0][1] = fma2(a01, wy, b2[0][1]);
                    b2[1][0] = fma2(a23, wx, b2[1][0]);
                    b2[1][1] = fma2(a23, wy, b2[1][1]);
                }
            }
            __syncwarp();
#pragma unroll
            for (int p = 0; p < 2; p++) {
                float x0, x1, y0, y1;
                unpack2(b2[p][0], x0, x1);
                unpack2(b2[p][1], y0, y1);
                float2 h0, h1;
                h0.x = silu_f(x0 * 0.125f); h0.y = silu_f(y0 * 0.125f);
                h1.x = silu_f(x1 * 0.125f); h1.y = silu_f(y1 * 0.125f);
                *(float2*)&hh[(2 * p) * 64 + 2 * lane]     = h0;
                *(float2*)&hh[(2 * p + 1) * 64 + 2 * lane] = h1;
            }
            __syncwarp();
        }

        // ---- layer 4 : h @ M4 -> tpw(256), column-pair packed f32x2 ----
        ull a4p[TPW][4];
#pragma unroll
        for (int t = 0; t < TPW; t++)
#pragma unroll
            for (int jp = 0; jp < 4; jp++) a4p[t][jp] = 0ull;
        for (int i = 0; i < 64; i += 4) {
            float ha[TPW][4];
#pragma unroll
            for (int t = 0; t < TPW; t++)
                *(float4*)ha[t] = *(const float4*)&hh[t * 64 + i];
#pragma unroll
            for (int k = 0; k < 4; k++) {
                const float* wr = &sM4[((i + k) << 8) + 2 * lane];
                ull wp0 = *(const ull*)(wr);
                ull wp1 = *(const ull*)(wr + 64);
                ull wp2 = *(const ull*)(wr + 128);
                ull wp3 = *(const ull*)(wr + 192);
#pragma unroll
                for (int t = 0; t < TPW; t++) {
                    ull aa = pack2(ha[t][k], ha[t][k]);
                    a4p[t][0] = fma2(aa, wp0, a4p[t][0]);
                    a4p[t][1] = fma2(aa, wp1, a4p[t][1]);
                    a4p[t][2] = fma2(aa, wp2, a4p[t][2]);
                    a4p[t][3] = fma2(aa, wp3, a4p[t][3]);
                }
            }
        }

        // ---- message construction + lane-coalesced scalar atomic scatter ----
#pragma unroll
        for (int t = 0; t < TPW; t++) {
            int e = e0 + t;
            int snd = __ldg(&snd_idx[e]);
            int rcv = __ldg(&rcv_idx[e]);
            float4 ea = __ldg((const float4*)(edge_attrs + (size_t)e * 4));
            float ys = ea.x, yv0 = ea.y, yv1 = ea.z, yv2 = ea.w;
            const float* sup = g_sup + (size_t)snd * 64;
            const float* vup = g_vup + (size_t)snd * 192;
            float* ms = g_msgs + (size_t)rcv * 128;
            float* mv = g_msgv + (size_t)rcv * 384;
            float w0a, w0b, w1a, w1b, w2a, w2b, w3a, w3b;
            unpack2(a4p[t][0], w0a, w0b);
            unpack2(a4p[t][1], w1a, w1b);
            unpack2(a4p[t][2], w2a, w2b);
            unpack2(a4p[t][3], w3a, w3b);
#pragma unroll
            for (int j = 0; j < 2; j++) {
                int u = lane + 32 * j;
                float xs  = __ldg(sup + u);
                float xv0 = __ldg(vup + 3 * u);
                float xv1 = __ldg(vup + 3 * u + 1);
                float xv2 = __ldg(vup + 3 * u + 2);
                float w0 = j ? w0b : w0a;
                float w1 = j ? w1b : w1a;
                float w2 = j ? w2b : w2a;
                float w3 = j ? w3b : w3a;
                float dv = xv0 * yv0 + xv1 * yv1 + xv2 * yv2;
                atomicAdd(ms + u,       w0 * xs * ys);
                atomicAdd(ms + 64 + u,  w3 * dv * INV_SQRT3);
                float wxs = w1 * xs;
                atomicAdd(mv + u,        wxs * yv0);
                atomicAdd(mv + 128 + u,  wxs * yv1);
                atomicAdd(mv + 256 + u,  wxs * yv2);
                float wys = w2 * ys;
                atomicAdd(mv + 64 + u,        wys * xv0);
                atomicAdd(mv + 128 + 64 + u,  wys * xv1);
                atomicAdd(mv + 256 + 64 + u,  wys * xv2);
            }
        }
    }
}

// ---------------------------------------------------------------------------
// Node output: out_s = S @ W_lin0 * sc ; out_v = einsum(num,uv->nvm) * sc
// ---------------------------------------------------------------------------
#define NODEOUT_SMEM ((8192 + 8192 + 16 * 512) * 4)

__global__ __launch_bounds__(256) void nodeout_kernel(
    const float* __restrict__ WL0, const float* __restrict__ WL1,
    float* __restrict__ out) {
    extern __shared__ float smem[];
    float* sW0 = smem;            // 128x64
    float* sW1 = sW0 + 8192;      // 128x64
    float* sS  = sW1 + 8192;      // 16 x 128
    float* sV  = sS + 16 * 128;   // 16 x 384
    int tid = threadIdx.x;
    const float SC = 0.0055242717280199021f;  // 1/(sqrt(128)*16)
    for (int i = tid; i < 8192; i += 256) { sW0[i] = WL0[i] * SC; sW1[i] = WL1[i] * SC; }
    int ln = tid >> 4;
    int cg = tid & 15;
    const float4* w0v = (const float4*)sW0;
    const float4* w1v = (const float4*)sW1;
    const int ntiles = N_NODES / 16;
    for (int tile = blockIdx.x; tile < ntiles; tile += gridDim.x) {
        int nb = tile * 16;
        __syncthreads();
        {
            const float4* srcS = (const float4*)(g_msgs + (size_t)nb * 128);
            float4* dstS = (float4*)sS;
            for (int i = tid; i < 512; i += 256) dstS[i] = srcS[i];
            const float4* srcV = (const float4*)(g_msgv + (size_t)nb * 384);
            float4* dstV = (float4*)sV;
            for (int i = tid; i < 1536; i += 256) dstV[i] = srcV[i];
        }
        __syncthreads();
        const float* S = sS + ln * 128;
        const float* V = sV + ln * 384;
        float4 aS = make_float4(0.f, 0.f, 0.f, 0.f);
        float4 a0 = aS, a1 = aS, a2 = aS;
#pragma unroll 4
        for (int u = 0; u < 128; u++) {
            float4 w0 = w0v[u * 16 + cg];
            float4 w1 = w1v[u * 16 + cg];
            float s  = S[u];
            float v0 = V[u], v1 = V[128 + u], v2 = V[256 + u];
            aS.x += s * w0.x; aS.y += s * w0.y; aS.z += s * w0.z; aS.w += s * w0.w;
            a0.x += v0 * w1.x; a0.y += v0 * w1.y; a0.z += v0 * w1.z; a0.w += v0 * w1.w;
            a1.x += v1 * w1.x; a1.y += v1 * w1.y; a1.z += v1 * w1.z; a1.w += v1 * w1.w;
            a2.x += v2 * w1.x; a2.y += v2 * w1.y; a2.z += v2 * w1.z; a2.w += v2 * w1.w;
        }
        int n = nb + ln;
        float* o = out + (size_t)n * 256;
        *(float4*)(o + 4 * cg) = aS;
        float* vp = o + 64 + 12 * cg;
        ((float4*)vp)[0] = make_float4(a0.x, a1.x, a2.x, a0.y);
        ((float4*)vp)[1] = make_float4(a1.y, a2.y, a0.z, a1.z);
        ((float4*)vp)[2] = make_float4(a2.z, a0.w, a1.w, a2.w);
    }
}

// ---------------------------------------------------------------------------
extern "C" void kernel_launch(void* const* d_in, const int* in_sizes, int n_in,
                              void* d_out, int out_size) {
    const float* node_feats = (const float*)d_in[1];
    const float* edge_attrs = (const float*)d_in[2];
    const float* edge_feats = (const float*)d_in[3];
    const int*   eidx       = (const int*)d_in[4];
    const float* W_up0      = (const float*)d_in[5];
    const float* W_up1      = (const float*)d_in[6];
    const float* M1         = (const float*)d_in[7];
    const float* M2         = (const float*)d_in[8];
    const float* M3         = (const float*)d_in[9];
    const float* M4         = (const float*)d_in[10];
    const float* WL0        = (const float*)d_in[11];
    const float* WL1        = (const float*)d_in[12];
    float* out = (float*)d_out;

    cudaFuncSetAttribute(edge_kernel,
                         cudaFuncAttributeMaxDynamicSharedMemorySize, EDGE_SMEM);
    cudaFuncSetAttribute(nodeout_kernel,
                         cudaFuncAttributeMaxDynamicSharedMemorySize, NODEOUT_SMEM);
    cudaFuncSetAttribute(nodeup_kernel,
                         cudaFuncAttributeMaxDynamicSharedMemorySize, NUP_SMEM);

    zero_kernel<<<256, 256>>>();
    nodeup_kernel<<<296, 256, NUP_SMEM>>>(node_feats, W_up0, W_up1);
    edge_kernel<<<296, 256, EDGE_SMEM>>>(edge_attrs, edge_feats,
                                         eidx, eidx + N_EDGES, M1, M2, M3, M4);
    nodeout_kernel<<<296, 256, NODEOUT_SMEM>>>(WL0, WL1, out);
}

// round 7
// speedup vs baseline: 2.1438x; 1.0886x over previous
#include <cuda_runtime.h>
#include <cstdint>

#define N_NODES 20000
#define N_EDGES 320000
#define TPW 8  // edges per warp per group

typedef unsigned long long ull;

// Scratch (device globals — no allocation allowed)
__device__ float g_sup[N_NODES * 64];    // up-projected scalars  [n][u]
__device__ float g_vup[N_NODES * 192];   // up-projected vectors  [n][u][m]
__device__ float g_msgs[N_NODES * 128];  // scalar messages       [n][u]   (m_s0 | m_s1)
__device__ float g_msgv[N_NODES * 384];  // vector messages       [n][m][p] (p<64: v0, p>=64: v1)

__device__ __forceinline__ float silu_f(float x) {
    return __fdividef(x, 1.0f + __expf(-x));
}

// ---- packed f32x2 helpers (sm_103a) ----
__device__ __forceinline__ ull pack2(float x, float y) {
    ull d; asm("mov.b64 %0, {%1, %2};" : "=l"(d) : "f"(x), "f"(y)); return d;
}
__device__ __forceinline__ void unpack2(ull v, float& x, float& y) {
    asm("mov.b64 {%0, %1}, %2;" : "=f"(x), "=f"(y) : "l"(v));
}
__device__ __forceinline__ ull fma2(ull a, ull b, ull c) {
    ull d; asm("fma.rn.f32x2 %0, %1, %2, %3;" : "=l"(d) : "l"(a), "l"(b), "l"(c)); return d;
}

// ---------------------------------------------------------------------------
// Zero the message accumulators
// ---------------------------------------------------------------------------
__global__ void zero_kernel() {
    int idx = blockIdx.x * blockDim.x + threadIdx.x;
    int stride = gridDim.x * blockDim.x;
    const int ns = N_NODES * 128 / 4;
    const int nv = N_NODES * 384 / 4;
    float4 z = make_float4(0.f, 0.f, 0.f, 0.f);
    for (int i = idx; i < ns; i += stride) ((float4*)g_msgs)[i] = z;
    for (int i = idx; i < nv; i += stride) ((float4*)g_msgv)[i] = z;
}

// ---------------------------------------------------------------------------
// Node up-projection: s' = s @ W_up0 / 8 ; v' = einsum(num,uv->nvm) / 8
// ---------------------------------------------------------------------------
#define NUP_SMEM ((4096 + 4096 + 16 * 256) * 4)

__global__ __launch_bounds__(256) void nodeup_kernel(
    const float* __restrict__ nf, const float* __restrict__ W0,
    const float* __restrict__ W1) {
    extern __shared__ float smem[];
    float* sW0 = smem;            // 64x64
    float* sW1 = sW0 + 4096;      // 64x64
    float* sx  = sW1 + 4096;      // 16 x 256
    int tid = threadIdx.x;
    for (int i = tid; i < 4096; i += 256) { sW0[i] = W0[i] * 0.125f; sW1[i] = W1[i] * 0.125f; }
    int ln = tid >> 4;          // local node 0..15
    int cg = tid & 15;          // col group (4 cols)
    const float4* w0v = (const float4*)sW0;
    const float4* w1v = (const float4*)sW1;
    const int ntiles = N_NODES / 16;
    for (int tile = blockIdx.x; tile < ntiles; tile += gridDim.x) {
        int nb = tile * 16;
        __syncthreads();
        {
            const float4* src = (const float4*)(nf + (size_t)nb * 256);
            float4* dst = (float4*)sx;
            for (int i = tid; i < 1024; i += 256) dst[i] = src[i];
        }
        __syncthreads();
        const float* x = sx + ln * 256;
        float4 aS = make_float4(0.f, 0.f, 0.f, 0.f);
        float4 a0 = aS, a1 = aS, a2 = aS;
#pragma unroll 4
        for (int u = 0; u < 64; u++) {
            float4 w0 = w0v[u * 16 + cg];
            float4 w1 = w1v[u * 16 + cg];
            float s  = x[u];
            float v0 = x[64 + 3 * u], v1 = x[64 + 3 * u + 1], v2 = x[64 + 3 * u + 2];
            aS.x += s * w0.x; aS.y += s * w0.y; aS.z += s * w0.z; aS.w += s * w0.w;
            a0.x += v0 * w1.x; a0.y += v0 * w1.y; a0.z += v0 * w1.z; a0.w += v0 * w1.w;
            a1.x += v1 * w1.x; a1.y += v1 * w1.y; a1.z += v1 * w1.z; a1.w += v1 * w1.w;
            a2.x += v2 * w1.x; a2.y += v2 * w1.y; a2.z += v2 * w1.z; a2.w += v2 * w1.w;
        }
        int n = nb + ln;
        *(float4*)(g_sup + (size_t)n * 64 + 4 * cg) = aS;
        float* vp = g_vup + (size_t)n * 192 + 12 * cg;
        ((float4*)vp)[0] = make_float4(a0.x, a1.x, a2.x, a0.y);
        ((float4*)vp)[1] = make_float4(a1.y, a2.y, a0.z, a1.z);
        ((float4*)vp)[2] = make_float4(a2.z, a0.w, a1.w, a2.w);
    }
}

// ---------------------------------------------------------------------------
// Fused edge kernel: MLP(8->64->64->64->256) -> message build -> atomic scatter
// TPW=8 edges per warp per weight sweep. Layers 1-3 plain FFMA; layer 4 as two
// column half-passes of packed f32x2, each followed by its half of the scatter.
// 512 threads / 1 CTA per SM.
// ---------------------------------------------------------------------------
#define EDGE_THREADS 512
#define EDGE_WARPS (EDGE_THREADS / 32)
#define EDGE_SMEM ((512 + 4096 + 4096 + 16384 + EDGE_WARPS * TPW * 64) * 4)

__global__ __launch_bounds__(EDGE_THREADS, 1) void edge_kernel(
    const float* __restrict__ edge_attrs, const float* __restrict__ edge_feats,
    const int* __restrict__ snd_idx, const int* __restrict__ rcv_idx,
    const float* __restrict__ M1, const float* __restrict__ M2,
    const float* __restrict__ M3, const float* __restrict__ M4) {
    extern __shared__ float smem[];
    float* sM1 = smem;
    float* sM2 = sM1 + 512;
    float* sM3 = sM2 + 4096;
    float* sM4 = sM3 + 4096;   // pair-permuted, pre-scaled by 1/8
    float* sh  = sM4 + 16384;
    int tid = threadIdx.x;
    for (int i = tid; i < 512;  i += EDGE_THREADS) sM1[i] = M1[i];
    for (int i = tid; i < 4096; i += EDGE_THREADS) { sM2[i] = M2[i]; sM3[i] = M3[i]; }
    // Permute M4: dest = i*256 + (jp*32 + l)*2 + half, where col = (2jp+half)*32 + l.
    for (int idx = tid; idx < 16384; idx += EDGE_THREADS) {
        int i = idx >> 8, c = idx & 255;
        int j = c >> 5, lc = c & 31, jp = j >> 1, half = j & 1;
        sM4[(i << 8) + (((jp << 5) + lc) << 1) + half] = M4[idx] * 0.125f;
    }
    __syncthreads();

    int warp = tid >> 5, lane = tid & 31;
    float* hh = sh + warp * (TPW * 64);
    const int ngroups = N_EDGES / TPW;
    const float INV_SQRT3 = 0.57735026918962576f;
    const float S1 = 0.35355339059327379f;  // 1/sqrt(8)

    // Layer-1 weights are tiny: keep this lane's two columns in registers.
    float2 w1r[8];
#pragma unroll
    for (int i = 0; i < 8; i++) w1r[i] = *(const float2*)&sM1[i * 64 + 2 * lane];

    for (int g = blockIdx.x * EDGE_WARPS + warp; g < ngroups; g += gridDim.x * EDGE_WARPS) {
        int e0 = g * TPW;
        // ---- layer 1 : ef(8) @ M1 -> h(64), silu ----
#pragma unroll
        for (int t = 0; t < TPW; t++) {
            const float4* p = (const float4*)(edge_feats + (size_t)(e0 + t) * 8);
            float4 A = __ldg(p), B = __ldg(p + 1);
            float a0 = A.x * w1r[0].x + A.y * w1r[1].x + A.z * w1r[2].x + A.w * w1r[3].x
                     + B.x * w1r[4].x + B.y * w1r[5].x + B.z * w1r[6].x + B.w * w1r[7].x;
            float a1 = A.x * w1r[0].y + A.y * w1r[1].y + A.z * w1r[2].y + A.w * w1r[3].y
                     + B.x * w1r[4].y + B.y * w1r[5].y + B.z * w1r[6].y + B.w * w1r[7].y;
            float2 hv;
            hv.x = silu_f(a0 * S1);
            hv.y = silu_f(a1 * S1);
            *(float2*)&hh[t * 64 + 2 * lane] = hv;
        }
        __syncwarp();

        // ---- layers 2 & 3 : plain FFMA, weights amortized over 8 edges ----
#pragma unroll
        for (int L = 0; L < 2; L++) {
            const float* W = (L == 0) ? sM2 : sM3;
            float a0[TPW], a1[TPW];
#pragma unroll
            for (int t = 0; t < TPW; t++) { a0[t] = 0.f; a1[t] = 0.f; }
            for (int i = 0; i < 64; i += 4) {
                float2 w[4];
#pragma unroll
                for (int k = 0; k < 4; k++) w[k] = *(const float2*)&W[(i + k) * 64 + 2 * lane];
#pragma unroll
                for (int t = 0; t < TPW; t++) {
                    float4 q = *(const float4*)&hh[t * 64 + i];
                    a0[t] += q.x * w[0].x + q.y * w[1].x + q.z * w[2].x + q.w * w[3].x;
                    a1[t] += q.x * w[0].y + q.y * w[1].y + q.z * w[2].y + q.w * w[3].y;
                }
            }
            __syncwarp();
#pragma unroll
            for (int t = 0; t < TPW; t++) {
                float2 hv;
                hv.x = silu_f(a0[t] * 0.125f);
                hv.y = silu_f(a1[t] * 0.125f);
                *(float2*)&hh[t * 64 + 2 * lane] = hv;
            }
            __syncwarp();
        }

        // ---- layer 4 + scatter : two column half-passes ----
        // pass p covers jp = 2p, 2p+1  (i.e. w(2p), w(2p+1))
#pragma unroll
        for (int p = 0; p < 2; p++) {
            ull a4[TPW][2];
#pragma unroll
            for (int t = 0; t < TPW; t++) { a4[t][0] = 0ull; a4[t][1] = 0ull; }
            for (int i = 0; i < 64; i += 4) {
                float ha[TPW][4];
#pragma unroll
                for (int t = 0; t < TPW; t++)
                    *(float4*)ha[t] = *(const float4*)&hh[t * 64 + i];
#pragma unroll
                for (int k = 0; k < 4; k++) {
                    const float* wr = &sM4[((i + k) << 8) + 2 * lane + p * 128];
                    ull wpa = *(const ull*)(wr);
                    ull wpb = *(const ull*)(wr + 64);
#pragma unroll
                    for (int t = 0; t < TPW; t++) {
                        ull aa = pack2(ha[t][k], ha[t][k]);
                        a4[t][0] = fma2(aa, wpa, a4[t][0]);
                        a4[t][1] = fma2(aa, wpb, a4[t][1]);
                    }
                }
            }
            // scatter this half
#pragma unroll
            for (int t = 0; t < TPW; t++) {
                int e = e0 + t;
                int snd = __ldg(&snd_idx[e]);
                int rcv = __ldg(&rcv_idx[e]);
                float4 ea = __ldg((const float4*)(edge_attrs + (size_t)e * 4));
                float ys = ea.x, yv0 = ea.y, yv1 = ea.z, yv2 = ea.w;
                const float* sup = g_sup + (size_t)snd * 64;
                const float* vup = g_vup + (size_t)snd * 192;
                float* ms = g_msgs + (size_t)rcv * 128;
                float* mv = g_msgv + (size_t)rcv * 384;
                float wAa, wAb, wBa, wBb;   // wA = w(2p), wB = w(2p+1), (j=0, j=1)
                unpack2(a4[t][0], wAa, wAb);
                unpack2(a4[t][1], wBa, wBb);
                if (p == 0) {
                    // w0 -> m_s0 (needs ys); w1 -> m_v0 (needs xs, yv)
#pragma unroll
                    for (int j = 0; j < 2; j++) {
                        int u = lane + 32 * j;
                        float xs = __ldg(sup + u);
                        float w0 = j ? wAb : wAa;
                        float w1 = j ? wBb : wBa;
                        atomicAdd(ms + u, w0 * xs * ys);
                        float wxs = w1 * xs;
                        atomicAdd(mv + u,       wxs * yv0);
                        atomicAdd(mv + 128 + u, wxs * yv1);
                        atomicAdd(mv + 256 + u, wxs * yv2);
                    }
                } else {
                    // w2 -> m_v1 (needs xv, ys); w3 -> m_s1 (needs dot(xv,yv))
#pragma unroll
                    for (int j = 0; j < 2; j++) {
                        int u = lane + 32 * j;
                        float xv0 = __ldg(vup + 3 * u);
                        float xv1 = __ldg(vup + 3 * u + 1);
                        float xv2 = __ldg(vup + 3 * u + 2);
                        float w2 = j ? wAb : wAa;
                        float w3 = j ? wBb : wBa;
                        float dv = xv0 * yv0 + xv1 * yv1 + xv2 * yv2;
                        atomicAdd(ms + 64 + u, w3 * dv * INV_SQRT3);
                        float wys = w2 * ys;
                        atomicAdd(mv + 64 + u,  wys * xv0);
                        atomicAdd(mv + 192 + u, wys * xv1);
                        atomicAdd(mv + 320 + u, wys * xv2);
                    }
                }
            }
        }
    }
}

// ---------------------------------------------------------------------------
// Node output: out_s = S @ W_lin0 * sc ; out_v = einsum(num,uv->nvm) * sc
// 32-node tiles, 2 nodes per thread (weight LDS amortized).
// ---------------------------------------------------------------------------
#define NODEOUT_SMEM ((8192 + 8192 + 32 * 512) * 4)

__global__ __launch_bounds__(256) void nodeout_kernel(
    const float* __restrict__ WL0, const float* __restrict__ WL1,
    float* __restrict__ out) {
    extern __shared__ float smem[];
    float* sW0 = smem;            // 128x64
    float* sW1 = sW0 + 8192;      // 128x64
    float* sS  = sW1 + 8192;      // 32 x 128
    float* sV  = sS + 32 * 128;   // 32 x 384
    int tid = threadIdx.x;
    const float SC = 0.0055242717280199021f;  // 1/(sqrt(128)*16)
    for (int i = tid; i < 8192; i += 256) { sW0[i] = WL0[i] * SC; sW1[i] = WL1[i] * SC; }
    int ln = tid >> 4;
    int cg = tid & 15;
    const float4* w0v = (const float4*)sW0;
    const float4* w1v = (const float4*)sW1;
    int nb = blockIdx.x * 32;   // 625 blocks, one 32-node tile each
    {
        const float4* srcS = (const float4*)(g_msgs + (size_t)nb * 128);
        float4* dstS = (float4*)sS;
        for (int i = tid; i < 1024; i += 256) dstS[i] = srcS[i];
        const float4* srcV = (const float4*)(g_msgv + (size_t)nb * 384);
        float4* dstV = (float4*)sV;
        for (int i = tid; i < 3072; i += 256) dstV[i] = srcV[i];
    }
    __syncthreads();
    const float* SA = sS + ln * 128;
    const float* SB = sS + (ln + 16) * 128;
    const float* VA = sV + ln * 384;
    const float* VB = sV + (ln + 16) * 384;
    float4 aSA = make_float4(0.f, 0.f, 0.f, 0.f);
    float4 a0A = aSA, a1A = aSA, a2A = aSA;
    float4 aSB = aSA, a0B = aSA, a1B = aSA, a2B = aSA;
#pragma unroll 4
    for (int u = 0; u < 128; u++) {
        float4 w0 = w0v[u * 16 + cg];
        float4 w1 = w1v[u * 16 + cg];
        {
            float s = SA[u];
            float v0 = VA[u], v1 = VA[128 + u], v2 = VA[256 + u];
            aSA.x += s * w0.x; aSA.y += s * w0.y; aSA.z += s * w0.z; aSA.w += s * w0.w;
            a0A.x += v0 * w1.x; a0A.y += v0 * w1.y; a0A.z += v0 * w1.z; a0A.w += v0 * w1.w;
            a1A.x += v1 * w1.x; a1A.y += v1 * w1.y; a1A.z += v1 * w1.z; a1A.w += v1 * w1.w;
            a2A.x += v2 * w1.x; a2A.y += v2 * w1.y; a2A.z += v2 * w1.z; a2A.w += v2 * w1.w;
        }
        {
            float s = SB[u];
            float v0 = VB[u], v1 = VB[128 + u], v2 = VB[256 + u];
            aSB.x += s * w0.x; aSB.y += s * w0.y; aSB.z += s * w0.z; aSB.w += s * w0.w;
            a0B.x += v0 * w1.x; a0B.y += v0 * w1.y; a0B.z += v0 * w1.z; a0B.w += v0 * w1.w;
            a1B.x += v1 * w1.x; a1B.y += v1 * w1.y; a1B.z += v1 * w1.z; a1B.w += v1 * w1.w;
            a2B.x += v2 * w1.x; a2B.y += v2 * w1.y; a2B.z += v2 * w1.z; a2B.w += v2 * w1.w;
        }
    }
#pragma unroll
    for (int h = 0; h < 2; h++) {
        int n = nb + ln + 16 * h;
        float4 aS = h ? aSB : aSA;
        float4 a0 = h ? a0B : a0A;
        float4 a1 = h ? a1B : a1A;
        float4 a2 = h ? a2B : a2A;
        float* o = out + (size_t)n * 256;
        *(float4*)(o + 4 * cg) = aS;
        float* vp = o + 64 + 12 * cg;
        ((float4*)vp)[0] = make_float4(a0.x, a1.x, a2.x, a0.y);
        ((float4*)vp)[1] = make_float4(a1.y, a2.y, a0.z, a1.z);
        ((float4*)vp)[2] = make_float4(a2.z, a0.w, a1.w, a2.w);
    }
}

// ---------------------------------------------------------------------------
extern "C" void kernel_launch(void* const* d_in, const int* in_sizes, int n_in,
                              void* d_out, int out_size) {
    const float* node_feats = (const float*)d_in[1];
    const float* edge_attrs = (const float*)d_in[2];
    const float* edge_feats = (const float*)d_in[3];
    const int*   eidx       = (const int*)d_in[4];
    const float* W_up0      = (const float*)d_in[5];
    const float* W_up1      = (const float*)d_in[6];
    const float* M1         = (const float*)d_in[7];
    const float* M2         = (const float*)d_in[8];
    const float* M3         = (const float*)d_in[9];
    const float* M4         = (const float*)d_in[10];
    const float* WL0        = (const float*)d_in[11];
    const float* WL1        = (const float*)d_in[12];
    float* out = (float*)d_out;

    cudaFuncSetAttribute(edge_kernel,
                         cudaFuncAttributeMaxDynamicSharedMemorySize, EDGE_SMEM);
    cudaFuncSetAttribute(nodeout_kernel,
                         cudaFuncAttributeMaxDynamicSharedMemorySize, NODEOUT_SMEM);
    cudaFuncSetAttribute(nodeup_kernel,
                         cudaFuncAttributeMaxDynamicSharedMemorySize, NUP_SMEM);

    zero_kernel<<<256, 256>>>();
    nodeup_kernel<<<296, 256, NUP_SMEM>>>(node_feats, W_up0, W_up1);
    edge_kernel<<<148, EDGE_THREADS, EDGE_SMEM>>>(edge_attrs, edge_feats,
                                                  eidx, eidx + N_EDGES,
                                                  M1, M2, M3, M4);
    nodeout_kernel<<<N_NODES / 32, 256, NODEOUT_SMEM>>>(WL0, WL1, out);
}